// round 8
// baseline (speedup 1.0000x reference)
#include <cuda_runtime.h>
#include <cuda_fp16.h>
#include <math.h>

#define B_     4
#define N_     2048
#define F_     16
#define HID_   32
#define H_     6
#define OUT_   16
#define BN_    (B_*N_)
#define MAXDEG 256
#define FULL   0xffffffffu

// ---------------- scratch ----------------
__device__ int     g_deg[N_];
__device__ int     g_colsP[(size_t)N_ * MAXDEG];        // padded CSR (2 MB)
// h1 fp16, 3 half2-planes: plane p holds heads (2p, 2p+1), layout [node*32+lane]
__device__ __half2 g_h1p[3][(size_t)BN_ * HID_];
__device__ float   g_s1f[H_ * BN_];                     // [h][node] layout
__device__ float   g_s2f[H_ * BN_];
__device__ __align__(16) __half g_h2h[BN_ * OUT_];
__device__ float   g_t1[BN_];
__device__ float   g_t2[BN_];

// ---------------- build padded CSR: float4 + warp scan ----------------
__global__ void k_build(const float* __restrict__ adj) {
    int row  = blockIdx.x * 8 + (threadIdx.x >> 5);
    int lane = threadIdx.x & 31;
    const float4* ar4 = (const float4*)(adj + (size_t)row * N_);
    int* dst = g_colsP + (size_t)row * MAXDEG;
    int w = 0;
    #pragma unroll 4
    for (int it = 0; it < N_ / 128; it++) {           // 128 columns per warp-iter
        int j0 = it * 128 + lane * 4;
        float4 v = ar4[it * 32 + lane];
        bool p0 = (v.x > 0.f) | (j0     == row);
        bool p1 = (v.y > 0.f) | (j0 + 1 == row);
        bool p2 = (v.z > 0.f) | (j0 + 2 == row);
        bool p3 = (v.w > 0.f) | (j0 + 3 == row);
        int c = (int)p0 + (int)p1 + (int)p2 + (int)p3;
        int incl = c;
        #pragma unroll
        for (int d = 1; d < 32; d <<= 1) {
            int t = __shfl_up_sync(FULL, incl, d);
            if (lane >= d) incl += t;
        }
        int pos = w + incl - c;                        // exclusive
        if (p0 && pos < MAXDEG) dst[pos++] = j0;
        if (p1 && pos < MAXDEG) dst[pos++] = j0 + 1;
        if (p2 && pos < MAXDEG) dst[pos++] = j0 + 2;
        if (p3 && pos < MAXDEG) dst[pos++] = j0 + 3;
        w += __shfl_sync(FULL, incl, 31);
    }
    if (lane == 0) g_deg[row] = min(w, MAXDEG);
}

// ---------------- layer 1 linear: warp per node, all 6 heads ----------------
__global__ void k_l1_linear(const float* __restrict__ x,
                            const float* __restrict__ W1,
                            const float* __restrict__ a1) {
    __shared__ float sW[H_ * F_ * HID_];   // 12 KB
    __shared__ float sa[H_ * 2 * HID_];
    int tid = threadIdx.x;
    for (int t = tid; t < H_ * F_ * HID_; t += 256) sW[t] = W1[t];
    for (int t = tid; t < H_ * 2 * HID_;  t += 256) sa[t] = a1[t];
    __syncthreads();

    int wslot = tid >> 5, lane = tid & 31;
    int row = blockIdx.x * 8 + wslot;

    float xv = (lane < F_) ? x[(size_t)row * F_ + lane] : 0.f;
    float acc[H_] = {0.f, 0.f, 0.f, 0.f, 0.f, 0.f};
    #pragma unroll
    for (int k = 0; k < F_; k++) {
        float xk = __shfl_sync(FULL, xv, k);
        #pragma unroll
        for (int h = 0; h < H_; h++)
            acc[h] = fmaf(xk, sW[h * F_ * HID_ + k * HID_ + lane], acc[h]);
    }
    #pragma unroll
    for (int p = 0; p < 3; p++)
        g_h1p[p][(size_t)row * HID_ + lane] = __floats2half2_rn(acc[2 * p], acc[2 * p + 1]);
    #pragma unroll
    for (int h = 0; h < H_; h++) {
        float p1 = acc[h] * sa[h * 2 * HID_ + lane];
        float p2 = acc[h] * sa[h * 2 * HID_ + HID_ + lane];
        #pragma unroll
        for (int d = 16; d; d >>= 1) {
            p1 += __shfl_xor_sync(FULL, p1, d);
            p2 += __shfl_xor_sync(FULL, p2, d);
        }
        if (lane == 0) {
            g_s1f[h * BN_ + row] = p1;     // [h][node] layout
            g_s2f[h * BN_ + row] = p2;
        }
    }
}

// ---------------- fused layer-1 attention + ELU + layer-2 linear ----------------
// block = 512 thr = 16 warps = 16 rows of one b. Dynamic smem (54.9 KB -> 3 blocks/SM):
//   [0)      half  s2h[6][2048]   24576 B
//   [24576)  float sW2[192*17]    13056 B
//   [37632)  float sa2[32]          128 B
//   [37760)  float sw[16][32][8]  16384 B  (per-neighbor head weights; reused for x1)
//   [54144)  int   sj[16][32]      2048 B
#define SM1_S2  0
#define SM1_W2  24576
#define SM1_A2  37632
#define SM1_SW  37760
#define SM1_SJ  54144
#define SM1_TOT 56192

__global__ void __launch_bounds__(512, 3) k_l1_attn(const float* __restrict__ W2,
                                                    const float* __restrict__ a2) {
    extern __shared__ char smem[];
    __half* s2h = (__half*)(smem + SM1_S2);
    float*  sW2 = (float*)(smem + SM1_W2);
    float*  sa2 = (float*)(smem + SM1_A2);
    float (*sw)[32][8] = (float (*)[32][8])(smem + SM1_SW);
    int   (*sj)[32]    = (int (*)[32])(smem + SM1_SJ);

    int tid = threadIdx.x;
    int b  = blockIdx.x >> 7;                 // 128 blocks per b
    int i0 = (blockIdx.x & 127) * 16;

    for (int t = tid; t < H_ * N_; t += 512) {
        int h = t >> 11, n = t & (N_ - 1);
        s2h[t] = __float2half(g_s2f[h * BN_ + b * N_ + n]);
    }
    for (int t = tid; t < 192 * 16; t += 512) sW2[(t >> 4) * 17 + (t & 15)] = W2[t];
    if (tid < 32) sa2[tid] = a2[tid];
    __syncthreads();

    int w = tid >> 5, lane = tid & 31;
    int i = i0 + w;
    int node_i = b * N_ + i;
    int deg = g_deg[i];
    const int* cols = g_colsP + (size_t)i * MAXDEG;

    float s1v[6];
    #pragma unroll
    for (int h = 0; h < 6; h++) s1v[h] = g_s1f[h * BN_ + node_i];

    const __half2* p0  = g_h1p[0];
    const __half2* p1p = g_h1p[1];
    const __half2* p2p = g_h1p[2];

    float acc[6] = {0.f, 0.f, 0.f, 0.f, 0.f, 0.f};
    float den[6] = {0.f, 0.f, 0.f, 0.f, 0.f, 0.f};

    for (int base = 0; base < deg; base += 32) {
        int lim = min(32, deg - base);
        if (lane < lim) {
            int j = cols[base + lane];
            sj[w][lane] = j;
            #pragma unroll
            for (int h = 0; h < 6; h++) {
                float e = s1v[h] + __half2float(s2h[h * N_ + j]);
                e = e > 0.f ? e : 0.2f * e;      // LeakyReLU
                float wt = __expf(e);            // no max-shift (|e| small, fp32 safe)
                den[h] += wt;
                sw[w][lane][h] = wt;
            }
        }
        __syncwarp();
        #define GBODY(T) {                                            \
            int nb = (b * N_ + sj[w][T]) * HID_ + lane;               \
            float4 w03 = *(const float4*)&sw[w][T][0];                \
            float2 w45 = *(const float2*)&sw[w][T][4];                \
            float2 f0 = __half22float2(p0[nb]);                       \
            float2 f1 = __half22float2(p1p[nb]);                      \
            float2 f2 = __half22float2(p2p[nb]);                      \
            acc[0] = fmaf(w03.x, f0.x, acc[0]);                       \
            acc[1] = fmaf(w03.y, f0.y, acc[1]);                       \
            acc[2] = fmaf(w03.z, f1.x, acc[2]);                       \
            acc[3] = fmaf(w03.w, f1.y, acc[3]);                       \
            acc[4] = fmaf(w45.x, f2.x, acc[4]);                       \
            acc[5] = fmaf(w45.y, f2.y, acc[5]); }
        if (lim == 32) {
            #pragma unroll 8
            for (int t = 0; t < 32; t++) GBODY(t)
        } else {
            for (int t = 0; t < lim; t++) GBODY(t)
        }
        #undef GBODY
        __syncwarp();
    }
    #pragma unroll
    for (int h = 0; h < 6; h++) {
        #pragma unroll
        for (int d = 16; d; d >>= 1) den[h] += __shfl_xor_sync(FULL, den[h], d);
    }
    // ELU(x1) into the (now free) sw slice: x1[h*32+lane] = v[h]
    #pragma unroll
    for (int h = 0; h < 6; h++) {
        float v = acc[h] / den[h];
        v = v > 0.f ? v : expm1f(v);
        sw[w][lane][h] = v;
    }
    __syncwarp();

    // layer-2 linear: lane -> output o over a 96-wide k half
    int o = lane & 15, half = lane >> 4;
    int cbase = half * 96;
    float hacc = 0.f;
    #pragma unroll
    for (int c = 0; c < 96; c++) {
        int cc = cbase + c;
        hacc = fmaf(sw[w][cc & 31][cc >> 5], sW2[cc * 17 + o], hacc);
    }
    hacc += __shfl_xor_sync(FULL, hacc, 16);      // combine k-halves: all lanes have h2[o]
    if (lane < 16) g_h2h[node_i * OUT_ + o] = __float2half(hacc);

    float q1 = hacc * sa2[o];
    float q2 = hacc * sa2[OUT_ + o];
    #pragma unroll
    for (int d = 8; d; d >>= 1) {
        q1 += __shfl_xor_sync(FULL, q1, d, 16);
        q2 += __shfl_xor_sync(FULL, q2, d, 16);
    }
    if (lane == 0) {
        g_t1[node_i] = q1;
        g_t2[node_i] = q2;
    }
}

// ---------------- layer-2 attention: half2 smem gather, 4 neighbors/round ----------------
// block = 512 thr = 16 rows of one b. Dynamic smem:
//   [0)      __half sh2[2048*16]  65536 B
//   [65536)  float  st2[2048]      8192 B
//   [73728)  float  sw[16][32]     2048 B
//   [75776)  int    sj[16][32]     2048 B
#define SM2_H2  0
#define SM2_T2  65536
#define SM2_SW  73728
#define SM2_SJ  75776
#define SM2_TOT 77824

__global__ void __launch_bounds__(512, 2) k_l2_attn(float* __restrict__ out) {
    extern __shared__ char smem[];
    __half2* sh2 = (__half2*)(smem + SM2_H2);      // [node*8 + o2]
    float*   st2 = (float*)(smem + SM2_T2);
    float (*sw)[32] = (float (*)[32])(smem + SM2_SW);
    int   (*sj)[32] = (int (*)[32])(smem + SM2_SJ);

    int tid = threadIdx.x;
    int b  = blockIdx.x >> 7;
    int i0 = (blockIdx.x & 127) * 16;

    {   // stage h2 (fp16, uint4 copy) and t2 for this b
        const uint4* src = (const uint4*)(g_h2h + (size_t)b * N_ * OUT_);
        uint4* dst = (uint4*)sh2;
        for (int t = tid; t < N_ * OUT_ * 2 / 16; t += 512) dst[t] = src[t];
        for (int t = tid; t < N_; t += 512) st2[t] = g_t2[b * N_ + t];
    }
    __syncthreads();

    int w = tid >> 5, lane = tid & 31;
    int i = i0 + w;
    int node_i = b * N_ + i;
    int deg = g_deg[i];
    const int* cols = g_colsP + (size_t)i * MAXDEG;
    float s1i = g_t1[node_i];

    int g  = lane >> 3;       // neighbor slot 0..3
    int o2 = lane & 7;        // output pair: outputs 2*o2, 2*o2+1
    float2 accA = {0.f, 0.f}, accB = {0.f, 0.f};
    float den = 0.f;

    for (int base = 0; base < deg; base += 32) {
        int lim = min(32, deg - base);
        if (lane < lim) {
            int j = cols[base + lane];
            float e = s1i + st2[j];
            e = e > 0.f ? e : 0.2f * e;
            float wt = __expf(e);
            den += wt;
            sw[w][lane] = wt;
            sj[w][lane] = j;
        }
        __syncwarp();
        int t = 0;
        for (; t + 8 <= lim; t += 8) {
            int ia = t + g, ib = t + 4 + g;
            float wa = sw[w][ia];
            float2 fa = __half22float2(sh2[sj[w][ia] * 8 + o2]);
            accA.x = fmaf(wa, fa.x, accA.x);
            accA.y = fmaf(wa, fa.y, accA.y);
            float wb = sw[w][ib];
            float2 fb = __half22float2(sh2[sj[w][ib] * 8 + o2]);
            accB.x = fmaf(wb, fb.x, accB.x);
            accB.y = fmaf(wb, fb.y, accB.y);
        }
        for (; t < lim; t += 4) {
            int ia = t + g;
            if (ia < lim) {
                float wa = sw[w][ia];
                float2 fa = __half22float2(sh2[sj[w][ia] * 8 + o2]);
                accA.x = fmaf(wa, fa.x, accA.x);
                accA.y = fmaf(wa, fa.y, accA.y);
            }
        }
        __syncwarp();
    }
    #pragma unroll
    for (int d = 16; d; d >>= 1) den += __shfl_xor_sync(FULL, den, d);
    accA.x += accB.x; accA.y += accB.y;
    #pragma unroll
    for (int d = 16; d >= 8; d >>= 1) {            // combine the 4 neighbor slots
        accA.x += __shfl_xor_sync(FULL, accA.x, d);
        accA.y += __shfl_xor_sync(FULL, accA.y, d);
    }
    if (lane < 8) {                                 // g==0 lanes hold full sums
        float vx = accA.x / den;
        float vy = accA.y / den;
        vx = vx > 0.f ? vx : expm1f(vx);            // ELU
        vy = vy > 0.f ? vy : expm1f(vy);
        *(float2*)(out + (size_t)node_i * OUT_ + 2 * o2) = make_float2(vx, vy);
    }
}

// ---------------- launch ----------------
extern "C" void kernel_launch(void* const* d_in, const int* in_sizes, int n_in,
                              void* d_out, int out_size) {
    const float* flow_x = (const float*)d_in[0];   // [4,2048,16]
    const float* adj    = (const float*)d_in[1];   // [2048,2048]
    const float* W1     = (const float*)d_in[2];   // [6,16,32]
    const float* a1     = (const float*)d_in[3];   // [6,64,1]
    const float* W2     = (const float*)d_in[4];   // [192,16]
    const float* a2     = (const float*)d_in[5];   // [32,1]
    float* out = (float*)d_out;

    cudaFuncSetAttribute(k_l1_attn, cudaFuncAttributeMaxDynamicSharedMemorySize, SM1_TOT);
    cudaFuncSetAttribute(k_l2_attn, cudaFuncAttributeMaxDynamicSharedMemorySize, SM2_TOT);

    k_build<<<N_ / 8, 256>>>(adj);
    k_l1_linear<<<BN_ / 8, 256>>>(flow_x, W1, a1);
    k_l1_attn<<<BN_ / 16, 512, SM1_TOT>>>(W2, a2);
    k_l2_attn<<<BN_ / 16, 512, SM2_TOT>>>(out);
}

// round 9
// speedup vs baseline: 1.0951x; 1.0951x over previous
#include <cuda_runtime.h>
#include <cuda_fp16.h>
#include <math.h>

#define B_     4
#define N_     2048
#define F_     16
#define HID_   32
#define H_     6
#define OUT_   16
#define BN_    (B_*N_)
#define MAXDEG 256
#define FULL   0xffffffffu

// ---------------- scratch ----------------
__device__ int     g_deg[N_];
__device__ int     g_colsP[(size_t)N_ * MAXDEG];        // padded CSR (2 MB)
// h1 fp16 packed: per (node,lane): heads 0-3 in uint2, heads 4-5 in uint
__device__ uint2   g_h1a[(size_t)BN_ * HID_];           // 2 MB
__device__ unsigned g_h1b[(size_t)BN_ * HID_];          // 1 MB
__device__ float   g_s1f[H_ * BN_];                     // [h][node] layout
__device__ float   g_s2f[H_ * BN_];
__device__ __align__(16) __half g_h2h[BN_ * OUT_];
__device__ float   g_t1[BN_];
__device__ float   g_t2[BN_];

// ---------------- build padded CSR: float4 + warp scan ----------------
__global__ void k_build(const float* __restrict__ adj) {
    int row  = blockIdx.x * 8 + (threadIdx.x >> 5);
    int lane = threadIdx.x & 31;
    const float4* ar4 = (const float4*)(adj + (size_t)row * N_);
    int* dst = g_colsP + (size_t)row * MAXDEG;
    int w = 0;
    #pragma unroll 4
    for (int it = 0; it < N_ / 128; it++) {           // 128 columns per warp-iter
        int j0 = it * 128 + lane * 4;
        float4 v = ar4[it * 32 + lane];
        bool p0 = (v.x > 0.f) | (j0     == row);
        bool p1 = (v.y > 0.f) | (j0 + 1 == row);
        bool p2 = (v.z > 0.f) | (j0 + 2 == row);
        bool p3 = (v.w > 0.f) | (j0 + 3 == row);
        int c = (int)p0 + (int)p1 + (int)p2 + (int)p3;
        int incl = c;
        #pragma unroll
        for (int d = 1; d < 32; d <<= 1) {
            int t = __shfl_up_sync(FULL, incl, d);
            if (lane >= d) incl += t;
        }
        int pos = w + incl - c;                        // exclusive
        if (p0 && pos < MAXDEG) dst[pos++] = j0;
        if (p1 && pos < MAXDEG) dst[pos++] = j0 + 1;
        if (p2 && pos < MAXDEG) dst[pos++] = j0 + 2;
        if (p3 && pos < MAXDEG) dst[pos++] = j0 + 3;
        w += __shfl_sync(FULL, incl, 31);
    }
    if (lane == 0) g_deg[row] = min(w, MAXDEG);
}

// ---------------- layer 1 linear: warp per node, all 6 heads ----------------
__global__ void k_l1_linear(const float* __restrict__ x,
                            const float* __restrict__ W1,
                            const float* __restrict__ a1) {
    __shared__ float sW[H_ * F_ * HID_];   // 12 KB
    __shared__ float sa[H_ * 2 * HID_];
    int tid = threadIdx.x;
    for (int t = tid; t < H_ * F_ * HID_; t += 256) sW[t] = W1[t];
    for (int t = tid; t < H_ * 2 * HID_;  t += 256) sa[t] = a1[t];
    __syncthreads();

    int wslot = tid >> 5, lane = tid & 31;
    int row = blockIdx.x * 8 + wslot;

    float xv = (lane < F_) ? x[(size_t)row * F_ + lane] : 0.f;
    float acc[H_] = {0.f, 0.f, 0.f, 0.f, 0.f, 0.f};
    #pragma unroll
    for (int k = 0; k < F_; k++) {
        float xk = __shfl_sync(FULL, xv, k);
        #pragma unroll
        for (int h = 0; h < H_; h++)
            acc[h] = fmaf(xk, sW[h * F_ * HID_ + k * HID_ + lane], acc[h]);
    }
    // packed fp16 feature stores
    {
        __half2 h01 = __floats2half2_rn(acc[0], acc[1]);
        __half2 h23 = __floats2half2_rn(acc[2], acc[3]);
        __half2 h45 = __floats2half2_rn(acc[4], acc[5]);
        uint2 a; a.x = *(unsigned*)&h01; a.y = *(unsigned*)&h23;
        g_h1a[(size_t)row * HID_ + lane] = a;
        g_h1b[(size_t)row * HID_ + lane] = *(unsigned*)&h45;
    }
    #pragma unroll
    for (int h = 0; h < H_; h++) {
        float p1 = acc[h] * sa[h * 2 * HID_ + lane];
        float p2 = acc[h] * sa[h * 2 * HID_ + HID_ + lane];
        #pragma unroll
        for (int d = 16; d; d >>= 1) {
            p1 += __shfl_xor_sync(FULL, p1, d);
            p2 += __shfl_xor_sync(FULL, p2, d);
        }
        if (lane == 0) {
            g_s1f[h * BN_ + row] = p1;     // [h][node] layout
            g_s2f[h * BN_ + row] = p2;
        }
    }
}

// ---------------- fused layer-1 attention + ELU + layer-2 linear ----------------
// block = 512 thr = 16 warps = 16 rows of one b. Dynamic smem:
//   [0)      half  s2h[6][2048]   24576 B
//   [24576)  float sW2[192*17]    13056 B
//   [37632)  float sa2[32]          128 B
//   [37760)  float sw[16][32][8]  16384 B  (per-neighbor head weights; reused for x1)
//   [54144)  int   sj[16][32]      2048 B
#define SM1_S2  0
#define SM1_W2  24576
#define SM1_A2  37632
#define SM1_SW  37760
#define SM1_SJ  54144
#define SM1_TOT 56192

__global__ void __launch_bounds__(512, 2) k_l1_attn(const float* __restrict__ W2,
                                                    const float* __restrict__ a2) {
    extern __shared__ char smem[];
    __half* s2h = (__half*)(smem + SM1_S2);
    float*  sW2 = (float*)(smem + SM1_W2);
    float*  sa2 = (float*)(smem + SM1_A2);
    float (*sw)[32][8] = (float (*)[32][8])(smem + SM1_SW);
    int   (*sj)[32]    = (int (*)[32])(smem + SM1_SJ);

    int tid = threadIdx.x;
    int b  = blockIdx.x >> 7;                 // 128 blocks per b
    int i0 = (blockIdx.x & 127) * 16;

    for (int t = tid; t < H_ * N_; t += 512) {
        int h = t >> 11, n = t & (N_ - 1);
        s2h[t] = __float2half(g_s2f[h * BN_ + b * N_ + n]);
    }
    for (int t = tid; t < 192 * 16; t += 512) sW2[(t >> 4) * 17 + (t & 15)] = W2[t];
    if (tid < 32) sa2[tid] = a2[tid];
    __syncthreads();

    int w = tid >> 5, lane = tid & 31;
    int i = i0 + w;
    int node_i = b * N_ + i;
    int deg = g_deg[i];
    const int* cols = g_colsP + (size_t)i * MAXDEG;

    float s1v[6];
    #pragma unroll
    for (int h = 0; h < 6; h++) s1v[h] = g_s1f[h * BN_ + node_i];

    const uint2*    fa = g_h1a + (size_t)b * N_ * HID_;
    const unsigned* fb = g_h1b + (size_t)b * N_ * HID_;

    float acc[6] = {0.f, 0.f, 0.f, 0.f, 0.f, 0.f};
    float den[6] = {0.f, 0.f, 0.f, 0.f, 0.f, 0.f};

    for (int base = 0; base < deg; base += 32) {
        int lim = min(32, deg - base);
        if (lane < lim) {
            int j = cols[base + lane];
            sj[w][lane] = j;
            float wt6[6];
            #pragma unroll
            for (int h = 0; h < 6; h++) {
                float e = s1v[h] + __half2float(s2h[h * N_ + j]);
                e = e > 0.f ? e : 0.2f * e;      // LeakyReLU
                float wt = __expf(e);            // no max-shift (|e| small, fp32 safe)
                den[h] += wt;
                wt6[h] = wt;
            }
            *(float4*)&sw[w][lane][0] = make_float4(wt6[0], wt6[1], wt6[2], wt6[3]);
            *(float2*)&sw[w][lane][4] = make_float2(wt6[4], wt6[5]);
        }
        __syncwarp();
        #define GBODY(T) {                                            \
            int nb = sj[w][T] * HID_ + lane;                          \
            float4 w03 = *(const float4*)&sw[w][T][0];                \
            float2 w45 = *(const float2*)&sw[w][T][4];                \
            uint2    va = fa[nb];                                     \
            unsigned vb = fb[nb];                                     \
            float2 f0 = __half22float2(*(const __half2*)&va.x);       \
            float2 f1 = __half22float2(*(const __half2*)&va.y);       \
            float2 f2 = __half22float2(*(const __half2*)&vb);         \
            acc[0] = fmaf(w03.x, f0.x, acc[0]);                       \
            acc[1] = fmaf(w03.y, f0.y, acc[1]);                       \
            acc[2] = fmaf(w03.z, f1.x, acc[2]);                       \
            acc[3] = fmaf(w03.w, f1.y, acc[3]);                       \
            acc[4] = fmaf(w45.x, f2.x, acc[4]);                       \
            acc[5] = fmaf(w45.y, f2.y, acc[5]); }
        if (lim == 32) {
            #pragma unroll 8
            for (int t = 0; t < 32; t++) GBODY(t)
        } else {
            for (int t = 0; t < lim; t++) GBODY(t)
        }
        #undef GBODY
        __syncwarp();
    }
    #pragma unroll
    for (int h = 0; h < 6; h++) {
        #pragma unroll
        for (int d = 16; d; d >>= 1) den[h] += __shfl_xor_sync(FULL, den[h], d);
    }
    // ELU(x1) into the (now free) sw slice: x1[h*32+lane] = v[h]
    #pragma unroll
    for (int h = 0; h < 6; h++) {
        float v = acc[h] / den[h];
        v = v > 0.f ? v : expm1f(v);
        sw[w][lane][h] = v;
    }
    __syncwarp();

    // layer-2 linear: lane -> output o over a 96-wide k half
    int o = lane & 15, half = lane >> 4;
    int cbase = half * 96;
    float hacc = 0.f;
    #pragma unroll
    for (int c = 0; c < 96; c++) {
        int cc = cbase + c;
        hacc = fmaf(sw[w][cc & 31][cc >> 5], sW2[cc * 17 + o], hacc);
    }
    hacc += __shfl_xor_sync(FULL, hacc, 16);      // combine k-halves: all lanes have h2[o]
    if (lane < 16) g_h2h[node_i * OUT_ + o] = __float2half(hacc);

    float q1 = hacc * sa2[o];
    float q2 = hacc * sa2[OUT_ + o];
    #pragma unroll
    for (int d = 8; d; d >>= 1) {
        q1 += __shfl_xor_sync(FULL, q1, d, 16);
        q2 += __shfl_xor_sync(FULL, q2, d, 16);
    }
    if (lane == 0) {
        g_t1[node_i] = q1;
        g_t2[node_i] = q2;
    }
}

// ---------------- layer-2 attention: half2 smem gather, 4 neighbors/round ----------------
// block = 512 thr = 16 rows of one b. Dynamic smem:
//   [0)      __half sh2[2048*16]  65536 B
//   [65536)  float  st2[2048]      8192 B
//   [73728)  float  sw[16][32]     2048 B
//   [75776)  int    sj[16][32]     2048 B
#define SM2_H2  0
#define SM2_T2  65536
#define SM2_SW  73728
#define SM2_SJ  75776
#define SM2_TOT 77824

__global__ void __launch_bounds__(512, 2) k_l2_attn(float* __restrict__ out) {
    extern __shared__ char smem[];
    __half2* sh2 = (__half2*)(smem + SM2_H2);      // [node*8 + o2]
    float*   st2 = (float*)(smem + SM2_T2);
    float (*sw)[32] = (float (*)[32])(smem + SM2_SW);
    int   (*sj)[32] = (int (*)[32])(smem + SM2_SJ);

    int tid = threadIdx.x;
    int b  = blockIdx.x >> 7;
    int i0 = (blockIdx.x & 127) * 16;

    {   // stage h2 (fp16, uint4 copy) and t2 for this b
        const uint4* src = (const uint4*)(g_h2h + (size_t)b * N_ * OUT_);
        uint4* dst = (uint4*)sh2;
        for (int t = tid; t < N_ * OUT_ * 2 / 16; t += 512) dst[t] = src[t];
        for (int t = tid; t < N_; t += 512) st2[t] = g_t2[b * N_ + t];
    }
    __syncthreads();

    int w = tid >> 5, lane = tid & 31;
    int i = i0 + w;
    int node_i = b * N_ + i;
    int deg = g_deg[i];
    const int* cols = g_colsP + (size_t)i * MAXDEG;
    float s1i = g_t1[node_i];

    int g  = lane >> 3;       // neighbor slot 0..3
    int o2 = lane & 7;        // output pair: outputs 2*o2, 2*o2+1
    float2 accA = {0.f, 0.f}, accB = {0.f, 0.f};
    float den = 0.f;

    for (int base = 0; base < deg; base += 32) {
        int lim = min(32, deg - base);
        if (lane < lim) {
            int j = cols[base + lane];
            float e = s1i + st2[j];
            e = e > 0.f ? e : 0.2f * e;
            float wt = __expf(e);
            den += wt;
            sw[w][lane] = wt;
            sj[w][lane] = j;
        }
        __syncwarp();
        int t = 0;
        for (; t + 8 <= lim; t += 8) {
            int ia = t + g, ib = t + 4 + g;
            float wa = sw[w][ia];
            float2 fav = __half22float2(sh2[sj[w][ia] * 8 + o2]);
            accA.x = fmaf(wa, fav.x, accA.x);
            accA.y = fmaf(wa, fav.y, accA.y);
            float wb = sw[w][ib];
            float2 fbv = __half22float2(sh2[sj[w][ib] * 8 + o2]);
            accB.x = fmaf(wb, fbv.x, accB.x);
            accB.y = fmaf(wb, fbv.y, accB.y);
        }
        for (; t < lim; t += 4) {
            int ia = t + g;
            if (ia < lim) {
                float wa = sw[w][ia];
                float2 fav = __half22float2(sh2[sj[w][ia] * 8 + o2]);
                accA.x = fmaf(wa, fav.x, accA.x);
                accA.y = fmaf(wa, fav.y, accA.y);
            }
        }
        __syncwarp();
    }
    #pragma unroll
    for (int d = 16; d; d >>= 1) den += __shfl_xor_sync(FULL, den, d);
    accA.x += accB.x; accA.y += accB.y;
    #pragma unroll
    for (int d = 16; d >= 8; d >>= 1) {            // combine the 4 neighbor slots
        accA.x += __shfl_xor_sync(FULL, accA.x, d);
        accA.y += __shfl_xor_sync(FULL, accA.y, d);
    }
    if (lane < 8) {                                 // g==0 lanes hold full sums
        float vx = accA.x / den;
        float vy = accA.y / den;
        vx = vx > 0.f ? vx : expm1f(vx);            // ELU
        vy = vy > 0.f ? vy : expm1f(vy);
        *(float2*)(out + (size_t)node_i * OUT_ + 2 * o2) = make_float2(vx, vy);
    }
}

// ---------------- launch ----------------
extern "C" void kernel_launch(void* const* d_in, const int* in_sizes, int n_in,
                              void* d_out, int out_size) {
    const float* flow_x = (const float*)d_in[0];   // [4,2048,16]
    const float* adj    = (const float*)d_in[1];   // [2048,2048]
    const float* W1     = (const float*)d_in[2];   // [6,16,32]
    const float* a1     = (const float*)d_in[3];   // [6,64,1]
    const float* W2     = (const float*)d_in[4];   // [192,16]
    const float* a2     = (const float*)d_in[5];   // [32,1]
    float* out = (float*)d_out;

    cudaFuncSetAttribute(k_l1_attn, cudaFuncAttributeMaxDynamicSharedMemorySize, SM1_TOT);
    cudaFuncSetAttribute(k_l2_attn, cudaFuncAttributeMaxDynamicSharedMemorySize, SM2_TOT);

    k_build<<<N_ / 8, 256>>>(adj);
    k_l1_linear<<<BN_ / 8, 256>>>(flow_x, W1, a1);
    k_l1_attn<<<BN_ / 16, 512, SM1_TOT>>>(W2, a2);
    k_l2_attn<<<BN_ / 16, 512, SM2_TOT>>>(out);
}

// round 12
// speedup vs baseline: 1.1718x; 1.0700x over previous
#include <cuda_runtime.h>
#include <cuda_fp16.h>
#include <math.h>

#define B_     4
#define N_     2048
#define F_     16
#define HID_   32
#define H_     6
#define OUT_   16
#define BN_    (B_*N_)
#define MAXDEG 256
#define FULL   0xffffffffu

// ---------------- scratch ----------------
__device__ int     g_deg[N_];
__device__ int     g_colsP[(size_t)N_ * MAXDEG];        // padded CSR (2 MB)
// h1 fp16 packed: per (node,lane): heads 0-3 in uint2, heads 4-5 in uint
__device__ uint2   g_h1a[(size_t)BN_ * HID_];           // 2 MB
__device__ unsigned g_h1b[(size_t)BN_ * HID_];          // 1 MB
__device__ float   g_s1f[H_ * BN_];                     // [h][node] layout
__device__ float   g_s2f[H_ * BN_];
__device__ __align__(32) __half g_h2h[BN_ * OUT_];      // 32B rows
__device__ float   g_t1[BN_];
__device__ float   g_t2[BN_];

// ---------------- build padded CSR: float4 + warp scan ----------------
__global__ void k_build(const float* __restrict__ adj) {
    int row  = blockIdx.x * 8 + (threadIdx.x >> 5);
    int lane = threadIdx.x & 31;
    const float4* ar4 = (const float4*)(adj + (size_t)row * N_);
    int* dst = g_colsP + (size_t)row * MAXDEG;
    int w = 0;
    #pragma unroll 4
    for (int it = 0; it < N_ / 128; it++) {           // 128 columns per warp-iter
        int j0 = it * 128 + lane * 4;
        float4 v = ar4[it * 32 + lane];
        bool p0 = (v.x > 0.f) | (j0     == row);
        bool p1 = (v.y > 0.f) | (j0 + 1 == row);
        bool p2 = (v.z > 0.f) | (j0 + 2 == row);
        bool p3 = (v.w > 0.f) | (j0 + 3 == row);
        int c = (int)p0 + (int)p1 + (int)p2 + (int)p3;
        int incl = c;
        #pragma unroll
        for (int d = 1; d < 32; d <<= 1) {
            int t = __shfl_up_sync(FULL, incl, d);
            if (lane >= d) incl += t;
        }
        int pos = w + incl - c;                        // exclusive
        if (p0 && pos < MAXDEG) dst[pos++] = j0;
        if (p1 && pos < MAXDEG) dst[pos++] = j0 + 1;
        if (p2 && pos < MAXDEG) dst[pos++] = j0 + 2;
        if (p3 && pos < MAXDEG) dst[pos++] = j0 + 3;
        w += __shfl_sync(FULL, incl, 31);
    }
    if (lane == 0) g_deg[row] = min(w, MAXDEG);
}

// ---------------- layer 1 linear: warp per node, all 6 heads ----------------
__global__ void k_l1_linear(const float* __restrict__ x,
                            const float* __restrict__ W1,
                            const float* __restrict__ a1) {
    __shared__ float sW[H_ * F_ * HID_];   // 12 KB
    __shared__ float sa[H_ * 2 * HID_];
    int tid = threadIdx.x;
    for (int t = tid; t < H_ * F_ * HID_; t += 256) sW[t] = W1[t];
    for (int t = tid; t < H_ * 2 * HID_;  t += 256) sa[t] = a1[t];
    __syncthreads();

    int wslot = tid >> 5, lane = tid & 31;
    int row = blockIdx.x * 8 + wslot;

    float xv = (lane < F_) ? x[(size_t)row * F_ + lane] : 0.f;
    float acc[H_] = {0.f, 0.f, 0.f, 0.f, 0.f, 0.f};
    #pragma unroll
    for (int k = 0; k < F_; k++) {
        float xk = __shfl_sync(FULL, xv, k);
        #pragma unroll
        for (int h = 0; h < H_; h++)
            acc[h] = fmaf(xk, sW[h * F_ * HID_ + k * HID_ + lane], acc[h]);
    }
    {
        __half2 h01 = __floats2half2_rn(acc[0], acc[1]);
        __half2 h23 = __floats2half2_rn(acc[2], acc[3]);
        __half2 h45 = __floats2half2_rn(acc[4], acc[5]);
        uint2 a; a.x = *(unsigned*)&h01; a.y = *(unsigned*)&h23;
        g_h1a[(size_t)row * HID_ + lane] = a;
        g_h1b[(size_t)row * HID_ + lane] = *(unsigned*)&h45;
    }
    #pragma unroll
    for (int h = 0; h < H_; h++) {
        float p1 = acc[h] * sa[h * 2 * HID_ + lane];
        float p2 = acc[h] * sa[h * 2 * HID_ + HID_ + lane];
        #pragma unroll
        for (int d = 16; d; d >>= 1) {
            p1 += __shfl_xor_sync(FULL, p1, d);
            p2 += __shfl_xor_sync(FULL, p2, d);
        }
        if (lane == 0) {
            g_s1f[h * BN_ + row] = p1;     // [h][node] layout
            g_s2f[h * BN_ + row] = p2;
        }
    }
}

// ---------------- fused layer-1 attention + ELU + layer-2 linear ----------------
// block = 512 thr = 16 warps = 16 rows of one b. Dynamic smem:
//   [0)      half  s2h[6][2048]   24576 B
//   [24576)  float sW2[192*17]    13056 B
//   [37632)  float sa2[32]          128 B
//   [37760)  float sw[16][32][8]  16384 B  (per-neighbor head weights; reused for x1)
//   [54144)  int   sj[16][32]      2048 B
#define SM1_S2  0
#define SM1_W2  24576
#define SM1_A2  37632
#define SM1_SW  37760
#define SM1_SJ  54144
#define SM1_TOT 56192

__global__ void __launch_bounds__(512, 2) k_l1_attn(const float* __restrict__ W2,
                                                    const float* __restrict__ a2) {
    extern __shared__ char smem[];
    __half* s2h = (__half*)(smem + SM1_S2);
    float*  sW2 = (float*)(smem + SM1_W2);
    float*  sa2 = (float*)(smem + SM1_A2);
    float (*sw)[32][8] = (float (*)[32][8])(smem + SM1_SW);
    int   (*sj)[32]    = (int (*)[32])(smem + SM1_SJ);

    int tid = threadIdx.x;
    int b  = blockIdx.x >> 7;                 // 128 blocks per b
    int i0 = (blockIdx.x & 127) * 16;

    for (int t = tid; t < H_ * N_; t += 512) {
        int h = t >> 11, n = t & (N_ - 1);
        s2h[t] = __float2half(g_s2f[h * BN_ + b * N_ + n]);
    }
    for (int t = tid; t < 192 * 16; t += 512) sW2[(t >> 4) * 17 + (t & 15)] = W2[t];
    if (tid < 32) sa2[tid] = a2[tid];
    __syncthreads();

    int w = tid >> 5, lane = tid & 31;
    int i = i0 + w;
    int node_i = b * N_ + i;
    int deg = g_deg[i];
    const int* cols = g_colsP + (size_t)i * MAXDEG;

    float s1v[6];
    #pragma unroll
    for (int h = 0; h < 6; h++) s1v[h] = g_s1f[h * BN_ + node_i];

    const uint2*    fa = g_h1a + (size_t)b * N_ * HID_;
    const unsigned* fb = g_h1b + (size_t)b * N_ * HID_;

    float acc[6] = {0.f, 0.f, 0.f, 0.f, 0.f, 0.f};
    float den[6] = {0.f, 0.f, 0.f, 0.f, 0.f, 0.f};

    for (int base = 0; base < deg; base += 32) {
        int lim = min(32, deg - base);
        if (lane < lim) {
            int j = cols[base + lane];
            sj[w][lane] = j;
            float wt6[6];
            #pragma unroll
            for (int h = 0; h < 6; h++) {
                float e = s1v[h] + __half2float(s2h[h * N_ + j]);
                e = e > 0.f ? e : 0.2f * e;      // LeakyReLU
                float wt = __expf(e);            // no max-shift (|e| small, fp32 safe)
                den[h] += wt;
                wt6[h] = wt;
            }
            *(float4*)&sw[w][lane][0] = make_float4(wt6[0], wt6[1], wt6[2], wt6[3]);
            *(float2*)&sw[w][lane][4] = make_float2(wt6[4], wt6[5]);
        }
        __syncwarp();
        #define GFMA(U) {                                                  \
            float4 w03 = *(const float4*)&sw[w][t0 + U][0];                \
            float2 w45 = *(const float2*)&sw[w][t0 + U][4];                \
            float2 f0 = __half22float2(*(const __half2*)&va[U].x);         \
            float2 f1 = __half22float2(*(const __half2*)&va[U].y);         \
            float2 f2 = __half22float2(*(const __half2*)&vb[U]);           \
            acc[0] = fmaf(w03.x, f0.x, acc[0]);                            \
            acc[1] = fmaf(w03.y, f0.y, acc[1]);                            \
            acc[2] = fmaf(w03.z, f1.x, acc[2]);                            \
            acc[3] = fmaf(w03.w, f1.y, acc[3]);                            \
            acc[4] = fmaf(w45.x, f2.x, acc[4]);                            \
            acc[5] = fmaf(w45.y, f2.y, acc[5]); }
        if (lim == 32) {
            #pragma unroll
            for (int t0 = 0; t0 < 32; t0 += 4) {       // batch 4: 8 LDGs in flight
                int nb0 = sj[w][t0]     * HID_ + lane;
                int nb1 = sj[w][t0 + 1] * HID_ + lane;
                int nb2 = sj[w][t0 + 2] * HID_ + lane;
                int nb3 = sj[w][t0 + 3] * HID_ + lane;
                uint2 va[4]; unsigned vb[4];
                va[0] = fa[nb0]; va[1] = fa[nb1]; va[2] = fa[nb2]; va[3] = fa[nb3];
                vb[0] = fb[nb0]; vb[1] = fb[nb1]; vb[2] = fb[nb2]; vb[3] = fb[nb3];
                GFMA(0) GFMA(1) GFMA(2) GFMA(3)
            }
        } else {
            for (int t0 = 0; t0 < lim; t0++) {
                int nb0 = sj[w][t0] * HID_ + lane;
                uint2 va0 = fa[nb0]; unsigned vb0 = fb[nb0];
                float4 w03 = *(const float4*)&sw[w][t0][0];
                float2 w45 = *(const float2*)&sw[w][t0][4];
                float2 f0 = __half22float2(*(const __half2*)&va0.x);
                float2 f1 = __half22float2(*(const __half2*)&va0.y);
                float2 f2 = __half22float2(*(const __half2*)&vb0);
                acc[0] = fmaf(w03.x, f0.x, acc[0]);
                acc[1] = fmaf(w03.y, f0.y, acc[1]);
                acc[2] = fmaf(w03.z, f1.x, acc[2]);
                acc[3] = fmaf(w03.w, f1.y, acc[3]);
                acc[4] = fmaf(w45.x, f2.x, acc[4]);
                acc[5] = fmaf(w45.y, f2.y, acc[5]);
            }
        }
        #undef GFMA
        __syncwarp();
    }
    #pragma unroll
    for (int h = 0; h < 6; h++) {
        #pragma unroll
        for (int d = 16; d; d >>= 1) den[h] += __shfl_xor_sync(FULL, den[h], d);
    }
    // ELU(x1) into the (now free) sw slice: x1[h*32+lane] = v[h]
    #pragma unroll
    for (int h = 0; h < 6; h++) {
        float v = acc[h] / den[h];
        v = v > 0.f ? v : expm1f(v);
        sw[w][lane][h] = v;
    }
    __syncwarp();

    // layer-2 linear: lane -> output o over a 96-wide k half
    int o = lane & 15, half = lane >> 4;
    int cbase = half * 96;
    float hacc = 0.f;
    #pragma unroll
    for (int c = 0; c < 96; c++) {
        int cc = cbase + c;
        hacc = fmaf(sw[w][cc & 31][cc >> 5], sW2[cc * 17 + o], hacc);
    }
    hacc += __shfl_xor_sync(FULL, hacc, 16);      // combine k-halves: all lanes have h2[o]
    if (lane < 16) g_h2h[node_i * OUT_ + o] = __float2half(hacc);

    float q1 = hacc * sa2[o];
    float q2 = hacc * sa2[OUT_ + o];
    #pragma unroll
    for (int d = 8; d; d >>= 1) {
        q1 += __shfl_xor_sync(FULL, q1, d, 16);
        q2 += __shfl_xor_sync(FULL, q2, d, 16);
    }
    if (lane == 0) {
        g_t1[node_i] = q1;
        g_t2[node_i] = q2;
    }
}

// ---------------- layer-2 attention: lane-per-neighbor, register accumulators ----------------
#define L2W 8
__global__ void __launch_bounds__(256) k_l2_attn(float* __restrict__ out) {
    __shared__ float red[L2W][16 * 33];    // padded transpose for final reduction (16.5 KB)
    int w = threadIdx.x >> 5, lane = threadIdx.x & 31;
    int gw = blockIdx.x * L2W + w;          // warp per (b, i)
    int i = gw & (N_ - 1), b = gw >> 11;
    int node_i = b * N_ + i;
    int deg = g_deg[i];
    const int* cols = g_colsP + (size_t)i * MAXDEG;
    float s1i = g_t1[node_i];
    const float* t2b = g_t2 + b * N_;
    const uint4* h2b = (const uint4*)(g_h2h + (size_t)b * N_ * OUT_);

    float acc[16];
    #pragma unroll
    for (int o = 0; o < 16; o++) acc[o] = 0.f;
    float den = 0.f;

    for (int t = lane; t < deg; t += 32) {   // each lane owns its neighbors
        int j = __ldg(cols + t);
        float e = s1i + __ldg(t2b + j);
        e = e > 0.f ? e : 0.2f * e;          // LeakyReLU
        float wt = __expf(e);
        den += wt;
        uint4 va = __ldg(h2b + j * 2);
        uint4 vb = __ldg(h2b + j * 2 + 1);
        float2 f;
        f = __half22float2(*(const __half2*)&va.x); acc[0]  = fmaf(wt, f.x, acc[0]);  acc[1]  = fmaf(wt, f.y, acc[1]);
        f = __half22float2(*(const __half2*)&va.y); acc[2]  = fmaf(wt, f.x, acc[2]);  acc[3]  = fmaf(wt, f.y, acc[3]);
        f = __half22float2(*(const __half2*)&va.z); acc[4]  = fmaf(wt, f.x, acc[4]);  acc[5]  = fmaf(wt, f.y, acc[5]);
        f = __half22float2(*(const __half2*)&va.w); acc[6]  = fmaf(wt, f.x, acc[6]);  acc[7]  = fmaf(wt, f.y, acc[7]);
        f = __half22float2(*(const __half2*)&vb.x); acc[8]  = fmaf(wt, f.x, acc[8]);  acc[9]  = fmaf(wt, f.y, acc[9]);
        f = __half22float2(*(const __half2*)&vb.y); acc[10] = fmaf(wt, f.x, acc[10]); acc[11] = fmaf(wt, f.y, acc[11]);
        f = __half22float2(*(const __half2*)&vb.z); acc[12] = fmaf(wt, f.x, acc[12]); acc[13] = fmaf(wt, f.y, acc[13]);
        f = __half22float2(*(const __half2*)&vb.w); acc[14] = fmaf(wt, f.x, acc[14]); acc[15] = fmaf(wt, f.y, acc[15]);
    }
    #pragma unroll
    for (int d = 16; d; d >>= 1) den += __shfl_xor_sync(FULL, den, d);

    // transpose-reduce: lane writes its 16 accs, then 16 lanes sum 32 each
    float* rw = red[w];
    #pragma unroll
    for (int o = 0; o < 16; o++) rw[o * 33 + lane] = acc[o];
    __syncwarp();
    if (lane < 16) {
        float s = 0.f;
        #pragma unroll
        for (int k = 0; k < 32; k++) s += rw[lane * 33 + k];
        float v = s / den;
        v = v > 0.f ? v : expm1f(v);          // ELU
        out[(size_t)node_i * OUT_ + lane] = v;
    }
}

// ---------------- launch ----------------
extern "C" void kernel_launch(void* const* d_in, const int* in_sizes, int n_in,
                              void* d_out, int out_size) {
    const float* flow_x = (const float*)d_in[0];   // [4,2048,16]
    const float* adj    = (const float*)d_in[1];   // [2048,2048]
    const float* W1     = (const float*)d_in[2];   // [6,16,32]
    const float* a1     = (const float*)d_in[3];   // [6,64,1]
    const float* W2     = (const float*)d_in[4];   // [192,16]
    const float* a2     = (const float*)d_in[5];   // [32,1]
    float* out = (float*)d_out;

    cudaFuncSetAttribute(k_l1_attn, cudaFuncAttributeMaxDynamicSharedMemorySize, SM1_TOT);

    k_build<<<N_ / 8, 256>>>(adj);
    k_l1_linear<<<BN_ / 8, 256>>>(flow_x, W1, a1);
    k_l1_attn<<<BN_ / 16, 512, SM1_TOT>>>(W2, a2);
    k_l2_attn<<<BN_ / L2W, 256>>>(out);
}